// round 16
// baseline (speedup 1.0000x reference)
#include <cuda_runtime.h>
#include <cuda_fp16.h>
#include <cstdint>

// Problem constants
#define T_    4
#define B_    32
#define C_    512
#define HW_   256
#define NH    8
#define HD    64
#define SLICE 4194304      // B*C*HW = one time slice
#define TOTAL 16777216     // T*B*C*HW
#define CN    131072       // C*HW per (t,b)

// ---------------------------------------------------------------------------
// helpers
// ---------------------------------------------------------------------------
__device__ __forceinline__ uint32_t smem_to_u32(const void* smem_ptr) {
    uint32_t addr;
    asm("{ .reg .u64 tmp; cvta.to.shared.u64 tmp, %1; cvt.u32.u64 %0, tmp; }"
        : "=r"(addr) : "l"(smem_ptr));
    return addr;
}

__device__ __forceinline__ void cp16(uint32_t dst, const void* src) {
    asm volatile("cp.async.ca.shared.global [%0], [%1], 16;" :: "r"(dst), "l"(src));
}

__device__ __forceinline__ void ldsm4(uint32_t* r, uint32_t addr) {
    asm volatile("ldmatrix.sync.aligned.m8n8.x4.shared.b16 {%0,%1,%2,%3}, [%4];"
                 : "=r"(r[0]), "=r"(r[1]), "=r"(r[2]), "=r"(r[3]) : "r"(addr));
}

__device__ __forceinline__ void ldsm4t(uint32_t* r, uint32_t addr) {
    asm volatile("ldmatrix.sync.aligned.m8n8.x4.trans.shared.b16 {%0,%1,%2,%3}, [%4];"
                 : "=r"(r[0]), "=r"(r[1]), "=r"(r[2]), "=r"(r[3]) : "r"(addr));
}

__device__ __forceinline__ void mma16816h(float* c, const uint32_t* a,
                                          uint32_t b0, uint32_t b1) {
    asm volatile(
        "mma.sync.aligned.m16n8k16.row.col.f32.f16.f16.f32 "
        "{%0,%1,%2,%3}, {%4,%5,%6,%7}, {%8,%9}, {%0,%1,%2,%3};"
        : "+f"(c[0]), "+f"(c[1]), "+f"(c[2]), "+f"(c[3])
        : "r"(a[0]), "r"(a[1]), "r"(a[2]), "r"(a[3]), "r"(b0), "r"(b1));
}

// streaming (evict-first) fp32x2 load/store for zero-reuse data
__device__ __forceinline__ float2 ldg_cs2(const float* p) {
    float2 v;
    asm volatile("ld.global.cs.v2.f32 {%0,%1}, [%2];"
                 : "=f"(v.x), "=f"(v.y) : "l"(p));
    return v;
}
__device__ __forceinline__ void stg_cs2(float* p, float2 v) {
    asm volatile("st.global.cs.v2.f32 [%0], {%1,%2};"
                 :: "l"(p), "f"(v.x), "f"(v.y) : "memory");
}

// ---------------------------------------------------------------------------
// Scratch (static device globals)
// ---------------------------------------------------------------------------
__device__ __half g_xsB[TOTAL];              // x spikes, per-b matrix [b][n'][c]
__device__ __half g_qs[TOTAL];               // q spikes, [t,b,c,n] fp16
__device__ __half g_ks[TOTAL];               // k spikes, [t,b,c,n] fp16
__device__ __half g_vs[TOTAL];               // v spikes, [t,b,c,n] fp16
__device__ __half g_x2T[TOTAL];              // x2 spikes, [tb][n][c] fp16
__device__ __half g_wsplit[2u * 2048u * 512u];      // [split: 0=mid',1=hi][2048][512]
__device__ float  g_scale[3 * C_];
__device__ float  g_bias [3 * C_];

// ---------------------------------------------------------------------------
// K1 (merged): blocks 0..1023  -> shortcut LIF + transpose (xsB [b][n'][c])
//              blocks 1024..2047 -> weight split (4 elems/thread) + sb concat
// ---------------------------------------------------------------------------
__global__ void prep_kernel(const float* __restrict__ x, __half* __restrict__ xsB,
                            const float* __restrict__ Wq, const float* __restrict__ Wk,
                            const float* __restrict__ Wv, const float* __restrict__ Wp,
                            __half* __restrict__ ws,
                            const float* __restrict__ qs, const float* __restrict__ qb,
                            const float* __restrict__ ks, const float* __restrict__ kb,
                            const float* __restrict__ vs, const float* __restrict__ vb,
                            float* __restrict__ gs, float* __restrict__ gb)
{
    __shared__ __half tile[64][65];
    int bid = blockIdx.x;
    int tid = threadIdx.x;

    if (bid >= 1024) {
        int base = (bid - 1024) * 1024 + tid * 4;
        int r = base >> 9;
        int kk = base & 511;
        const float* W = (r < 512) ? Wq : (r < 1024) ? Wk : (r < 1536) ? Wv : Wp;
        const float4 w4 = *(const float4*)&W[(size_t)(r & 511) * 512 + kk];
        const float wv[4] = {w4.x, w4.y, w4.z, w4.w};
        __half hi4[4], mid4[4];
#pragma unroll
        for (int u = 0; u < 4; u++) {
            __half hi = __float2half_rn(wv[u]);
            float r1 = wv[u] - __half2float(hi);
            hi4[u] = hi;
            mid4[u] = __float2half_rn(r1 * 4096.0f);
        }
        *(uint2*)&ws[base]             = *(uint2*)mid4;
        *(uint2*)&ws[1048576u + base]  = *(uint2*)hi4;

        int i = (bid - 1024) * 256 + tid;
        if (i < 512) {
            gs[i] = qs[i];               gb[i] = qb[i];
            gs[i + 512]  = ks[i];        gb[i + 512]  = kb[i];
            gs[i + 1024] = vs[i];        gb[i + 1024] = vb[i];
        }
        return;
    }

    int nblk = bid & 3, cblk = (bid >> 2) & 7, b = bid >> 5;

    float v[16];
#pragma unroll
    for (int p = 0; p < 16; p++) v[p] = 0.f;

    __half* D = xsB + (size_t)b * (1024 * 512);

#pragma unroll
    for (int t = 0; t < T_; t++) {
        if (t) __syncthreads();
#pragma unroll
        for (int p = 0; p < 16; p++) {
            int c_l = p * 4 + (tid >> 6), n_l = tid & 63;
            float xv = x[(size_t)t * SLICE +
                         ((size_t)(b * C_ + cblk * 64 + c_l)) * HW_ + nblk * 64 + n_l];
            v[p] = v[p] + (xv - v[p]) * 0.5f;
            float s = (v[p] >= 1.0f) ? 1.0f : 0.0f;
            if (s != 0.f) v[p] = 0.f;
            tile[c_l][n_l] = __float2half(s);
        }
        __syncthreads();
#pragma unroll
        for (int p = 0; p < 16; p++) {
            int c_l = tid & 63, n_l = p * 4 + (tid >> 6);
            int n = nblk * 64 + n_l;
            int nprime = (n >> 3) * 32 + t * 8 + (n & 7);
            D[(size_t)nprime * C_ + cblk * 64 + c_l] = tile[c_l][n_l];
        }
    }
}

// ---------------------------------------------------------------------------
// HMMA GEMM: CTA 128x128, 2x4 warps of 64x32, TWO-stage double buffer (r6 loop)
// MODE 0: qkv, 16 stages (8 mid' + 8 hi, exact). Epilogue: BN -> LIF(vth=1)
//         -> q/k/v [t,b,c,n] + vout. grid (8 nblk, 12 mtile, 32 b)
// MODE 1: proj, hi-split only (8 stages). Direct epilogue (r13) with
//         streaming (.cs) identity loads + out stores. grid (2,4,128)
// ---------------------------------------------------------------------------
#define STAGE_BYTES 36864
#define A_BYTES     18432
#define SM_STRIDE   136          // halves; 272B row stride (MODE0 epilogue)

template<int MODE>
__global__ void __launch_bounds__(256, 2) gemm_hmma_kernel(
    const __half* __restrict__ wsplit,            // [2][2048][512]
    const __half* __restrict__ Bmat,              // MODE0: xsB ; MODE1: x2T
    __half* __restrict__ qsp, __half* __restrict__ ksp, __half* __restrict__ vsp,
    float* __restrict__ vout,
    const float* __restrict__ scale, const float* __restrict__ bias,
    const float* __restrict__ cbias, const float* __restrict__ identity,
    float* __restrict__ outp, int wrow_base)
{
    constexpr int NS = (MODE == 0) ? 16 : 8;
    extern __shared__ __align__(128) char smem[];
    uint32_t smem_u = smem_to_u32(smem);
    const int tid = threadIdx.x;
    const int wid = tid >> 5, lane = tid & 31;
    const int wm = wid >> 2, wn = wid & 3;         // 2 x 4 warp grid, 64x32 tiles
    const int n0 = blockIdx.x * 128;
    const int m0 = blockIdx.y * 128;
    const int bz = blockIdx.z;
    const char* Bbase = (MODE == 0)
        ? (const char*)(Bmat + (size_t)bz * (1024 * 512))
        : (const char*)(Bmat + (size_t)bz * CN);

    float acc[4][4][4];
#pragma unroll
    for (int i = 0; i < 4; i++)
#pragma unroll
        for (int j = 0; j < 4; j++)
#pragma unroll
            for (int e = 0; e < 4; e++) acc[i][j][e] = 0.f;

    auto cp_stage = [&](int s) {
        int buf = s & 1;
        int split = (MODE == 0) ? (s >> 3) : 1;   // MODE1: hi only
        int kA = (s & 7) << 6;
        const char* Ag = (const char*)wsplit
                       + ((size_t)split * 2048 + (size_t)(wrow_base + m0)) * 1024
                       + (size_t)kA * 2;
        const char* Bg = Bbase + (size_t)n0 * 1024 + (size_t)kA * 2;
        uint32_t sA = smem_u + buf * STAGE_BYTES;
        uint32_t sB = sA + A_BYTES;
#pragma unroll
        for (int p = 0; p < 4; p++) {
            int lin = p * 256 + tid;
            int r = lin >> 3, sg = lin & 7;
            cp16(sA + r * 144 + sg * 16, Ag + (size_t)r * 1024 + sg * 16);
            cp16(sB + r * 144 + sg * 16, Bg + (size_t)r * 1024 + sg * 16);
        }
        asm volatile("cp.async.commit_group;");
    };

    cp_stage(0);

    for (int s = 0; s < NS; s++) {
        if (s + 1 < NS) {
            cp_stage(s + 1);
            asm volatile("cp.async.wait_group 1;");
        } else {
            asm volatile("cp.async.wait_group 0;");
        }
        __syncthreads();

        uint32_t sA = smem_u + (s & 1) * STAGE_BYTES;
        uint32_t sB = sA + A_BYTES;

#pragma unroll
        for (int kk = 0; kk < 4; kk++) {
            uint32_t a[4][4];
#pragma unroll
            for (int i = 0; i < 4; i++) {
                uint32_t row = wm * 64 + i * 16 + (lane & 15);
                uint32_t col = kk * 16 + ((lane >> 4) << 3);
                ldsm4(a[i], sA + (row * 72 + col) * 2);
            }
            uint32_t bf[2][4];
#pragma unroll
            for (int j2 = 0; j2 < 2; j2++) {
                uint32_t row = wn * 32 + j2 * 16 + (lane & 7) + ((lane >> 4) << 3);
                uint32_t col = kk * 16 + (((lane >> 3) & 1) << 3);
                ldsm4(bf[j2], sB + (row * 72 + col) * 2);
            }
#pragma unroll
            for (int i = 0; i < 4; i++)
#pragma unroll
                for (int jj = 0; jj < 4; jj++) {
                    uint32_t b0 = bf[jj >> 1][(jj & 1) * 2 + 0];
                    uint32_t b1 = bf[jj >> 1][(jj & 1) * 2 + 1];
                    mma16816h(acc[i][jj], a[i], b0, b1);
                }
        }
        if (MODE == 0 && s == 7) {
#pragma unroll
            for (int i = 0; i < 4; i++)
#pragma unroll
                for (int j = 0; j < 4; j++)
#pragma unroll
                    for (int e = 0; e < 4; e++) acc[i][j][e] *= 0.000244140625f;
        }
        __syncthreads();
    }

    int g = lane >> 2, tg = lane & 3;

    if (MODE == 0) {
        // ---- BN + LIF (vth=1) in registers: jj == t ----
        __half (*sm)[SM_STRIDE] = (__half(*)[SM_STRIDE])smem;
#pragma unroll
        for (int i = 0; i < 4; i++) {
#pragma unroll
            for (int eh = 0; eh < 2; eh++) {
                int rl = wm * 64 + i * 16 + g + eh * 8;
                float sc = scale[m0 + rl], bi = bias[m0 + rl];
#pragma unroll
                for (int e1 = 0; e1 < 2; e1++) {
                    int nl = wn * 8 + 2 * tg + e1;        // n_local 0..31
                    float v = 0.f;
#pragma unroll
                    for (int t = 0; t < T_; t++) {
                        float xv = acc[i][t][eh * 2 + e1] * sc + bi;
                        v = v + (xv - v) * 0.5f;
                        float ss = (v >= 1.0f) ? 1.0f : 0.0f;
                        if (ss != 0.f) v = 0.f;
                        sm[rl][t * 32 + nl] = __float2half(ss);
                    }
                }
            }
        }
        __syncthreads();

        int tt   = blockIdx.y >> 2;      // 0 q, 1 k, 2 v
        int msub = blockIdx.y & 3;       // 128-row block within tensor
        int b    = bz;
        int nb   = blockIdx.x;           // n base = nb*32

        __half* base = (tt == 0) ? qsp : (tt == 1) ? ksp : vsp;
#pragma unroll
        for (int p = 0; p < 2; p++) {
            int rid = p * 256 + tid;       // 0..511
            int t = rid >> 7, cl = rid & 127;
            const uint4* srow = (const uint4*)&sm[cl][t * 32];
            __half* dst = base + (size_t)t * SLICE
                        + ((size_t)(b * C_ + msub * 128 + cl)) * HW_ + nb * 32;
#pragma unroll
            for (int u = 0; u < 4; u++) ((uint4*)dst)[u] = srow[u];
        }
        if (tt == 2) {
            // vout fp32 [t,b,h,n,hd]
            int t = tid >> 6, rem = tid & 63;
            int hl = rem >> 5, n = rem & 31;
            int h = msub * 2 + hl;
            float* dst = vout + ((((size_t)(t * 32 + b) * NH + h) * HW_) + nb * 32 + n) * HD;
#pragma unroll
            for (int c4 = 0; c4 < 16; c4++) {
                float4 f;
                f.x = __half2float(sm[hl * 64 + c4 * 4 + 0][t * 32 + n]);
                f.y = __half2float(sm[hl * 64 + c4 * 4 + 1][t * 32 + n]);
                f.z = __half2float(sm[hl * 64 + c4 * 4 + 2][t * 32 + n]);
                f.w = __half2float(sm[hl * 64 + c4 * 4 + 3][t * 32 + n]);
                ((float4*)dst)[c4] = f;
            }
        }
    } else {
        // ---- proj epilogue (r13 form; streaming hints on identity/out) ----
#pragma unroll
        for (int i = 0; i < 4; i++) {
            int mloc = m0 + wm * 64 + i * 16 + g;
#pragma unroll
            for (int half = 0; half < 2; half++) {
                int c = mloc + half * 8;
                float sc = scale[c], bi = bias[c], cb = cbias[c];
                float* dst = outp + (size_t)bz * CN + (size_t)c * HW_;
                const float* idp = identity + (size_t)bz * CN + (size_t)c * HW_;
#pragma unroll
                for (int jj = 0; jj < 4; jj++) {
                    int col = n0 + wn * 32 + jj * 8 + 2 * tg;
                    float2 id2 = ldg_cs2(&idp[col]);
                    float2 v2;
                    v2.x = (acc[i][jj][half * 2 + 0] + cb) * sc + bi + id2.x;
                    v2.y = (acc[i][jj][half * 2 + 1] + cb) * sc + bi + id2.y;
                    stg_cs2(&dst[col], v2);
                }
            }
        }
    }
}

// ---------------------------------------------------------------------------
// FUSED attn + x2 kernel, one CTA per (h, b), 256 threads. (r13, unchanged)
// ---------------------------------------------------------------------------
#define FA_AT    0
#define FA_WORK  18432
#define FA_SQ    18432
#define FA_SX    35840
#define FA_TOTAL 55296
#define SQN      136

__global__ void __launch_bounds__(256) attn_x2_kernel(
    const __half* __restrict__ ksp, const __half* __restrict__ vsp,
    const __half* __restrict__ qsp, __half* __restrict__ x2T)
{
    extern __shared__ __align__(128) char fsm[];
    uint32_t smem_u = smem_to_u32(fsm);
    int h = blockIdx.x, b = blockIdx.y;
    int tid = threadIdx.x;
    int wid = tid >> 5, lane = tid & 31;
    int g = lane >> 2, tg = lane & 3;

    // ---------------- Phase A: attn ----------------
    {
        int group = tid >> 7;
        int gtid = tid & 127;
        int gwid = gtid >> 5;
        uint32_t sv_u = smem_u + FA_WORK + group * 18432;
        uint32_t sk_u = sv_u + 9216;
        char* sv_c = fsm + FA_WORK + group * 18432;
        char* sk_c = sv_c + 9216;

        float acc[8][4];
#pragma unroll
        for (int j = 0; j < 8; j++)
#pragma unroll
            for (int e = 0; e < 4; e++) acc[j][e] = 0.f;

        for (int st = 0; st < 8; st++) {
            int t = group * 2 + (st >> 2);
            int n0 = (st & 3) * 64;
            size_t base = (size_t)t * SLICE + ((size_t)(b * C_ + h * HD)) * HW_ + n0;
#pragma unroll
            for (int l = 0; l < 4; l++) {
                int lin = l * 128 + gtid;
                int r = lin >> 3, sg = lin & 7;
                *(uint4*)(sv_c + r * 144 + sg * 16) =
                    *(const uint4*)(vsp + base + (size_t)r * HW_ + sg * 8);
                *(uint4*)(sk_c + r * 144 + sg * 16) =
                    *(const uint4*)(ksp + base + (size_t)r * HW_ + sg * 8);
            }
            __syncthreads();

#pragma unroll
            for (int kk = 0; kk < 4; kk++) {
                uint32_t a[4];
                {
                    uint32_t row = gwid * 16 + (lane & 15);
                    uint32_t col = kk * 16 + ((lane >> 4) << 3);
                    ldsm4(a, sv_u + (row * 72 + col) * 2);
                }
                uint32_t bf[4][4];
#pragma unroll
                for (int j2 = 0; j2 < 4; j2++) {
                    uint32_t row = j2 * 16 + (lane & 7) + ((lane >> 4) << 3);
                    uint32_t col = kk * 16 + (((lane >> 3) & 1) << 3);
                    ldsm4(bf[j2], sk_u + (row * 72 + col) * 2);
                }
#pragma unroll
                for (int j = 0; j < 8; j++)
                    mma16816h(acc[j], a, bf[j >> 1][(j & 1) * 2], bf[j >> 1][(j & 1) * 2 + 1]);
            }
            __syncthreads();
        }

        char* at_c = fsm + FA_AT + group * 9216;
#pragma unroll
        for (int j = 0; j < 8; j++)
#pragma unroll
            for (int e = 0; e < 2; e++) {
                int row = gwid * 16 + g + e * 8;
                int col = j * 8 + tg * 2;
                __half2 h2 = __floats2half2_rn(acc[j][e * 2] * 0.0625f,
                                               acc[j][e * 2 + 1] * 0.0625f);
                *(__half2*)(at_c + (row * 72 + col) * 2) = h2;
            }
    }
    __syncthreads();

    // ---------------- Phase B: x2 ----------------
    int wm = wid >> 1, wn = wid & 1;
    uint32_t sq_u = smem_u + FA_SQ;
    __half (*sx)[72] = (__half(*)[72])(fsm + FA_SX);

    for (int nhalf = 0; nhalf < 2; nhalf++) {
        float mem[8][4];
#pragma unroll
        for (int j = 0; j < 8; j++)
#pragma unroll
            for (int e = 0; e < 4; e++) mem[j][e] = 0.f;

#pragma unroll
        for (int t = 0; t < T_; t++) {
            uint32_t sa_u = smem_u + FA_AT + (t >> 1) * 9216;
            {
                const __half* qp = qsp + (size_t)t * SLICE
                                 + ((size_t)(b * C_ + h * HD)) * HW_ + nhalf * 128;
#pragma unroll
                for (int l = 0; l < 4; l++) {
                    int lin = l * 256 + tid;
                    int r = lin >> 4, sg = lin & 15;
                    *(uint4*)(fsm + FA_SQ + r * (SQN * 2) + sg * 16) =
                        *(const uint4*)(qp + (size_t)r * HW_ + sg * 8);
                }
            }
            __syncthreads();

            float acc[8][4];
#pragma unroll
            for (int j = 0; j < 8; j++)
#pragma unroll
                for (int e = 0; e < 4; e++) acc[j][e] = 0.f;

#pragma unroll
            for (int kk = 0; kk < 4; kk++) {
                uint32_t a[4];
                {
                    uint32_t row = wm * 16 + (lane & 15);
                    uint32_t col = kk * 16 + ((lane >> 4) << 3);
                    ldsm4(a, sa_u + (row * 72 + col) * 2);
                }
                uint32_t bf[4][4];
#pragma unroll
                for (int j2 = 0; j2 < 4; j2++) {
                    uint32_t krow = kk * 16 + (((lane >> 3) & 1) << 3) + (lane & 7);
                    uint32_t ncol = wn * 64 + j2 * 16 + ((lane >> 4) << 3);
                    ldsm4t(bf[j2], sq_u + (krow * SQN + ncol) * 2);
                }
#pragma unroll
                for (int j = 0; j < 8; j++)
                    mma16816h(acc[j], a, bf[j >> 1][(j & 1) * 2], bf[j >> 1][(j & 1) * 2 + 1]);
            }

#pragma unroll
            for (int j = 0; j < 8; j++)
#pragma unroll
                for (int e = 0; e < 4; e++) {
                    float xv = acc[j][e];
                    mem[j][e] = mem[j][e] + (xv - mem[j][e]) * 0.5f;
                    float s = (mem[j][e] >= 0.5f) ? 1.0f : 0.0f;
                    if (s != 0.f) mem[j][e] = 0.f;
                    int n = wn * 64 + j * 8 + tg * 2 + (e & 1);
                    int de = wm * 16 + g + ((e >> 1) << 3);
                    sx[n][de] = __float2half(s);
                }
            __syncthreads();

            {
                __half* obase = x2T + ((size_t)(t * B_ + b) * HW_ + nhalf * 128) * C_ + h * HD;
#pragma unroll
                for (int l = 0; l < 2; l++) {
                    int idx = l * 256 + tid;
                    int n = idx >> 2, seg = idx & 3;
                    *(uint4*)(obase + (size_t)n * C_ + seg * 16) =
                        *(const uint4*)(&sx[n][seg * 16]);
                }
            }
            __syncthreads();
        }
    }
}

// ---------------------------------------------------------------------------
extern "C" void kernel_launch(void* const* d_in, const int* in_sizes, int n_in,
                              void* d_out, int out_size)
{
    const float* x       = (const float*)d_in[0];
    const float* Wq      = (const float*)d_in[1];
    const float* q_scale = (const float*)d_in[2];
    const float* q_bias  = (const float*)d_in[3];
    const float* Wk      = (const float*)d_in[4];
    const float* k_scale = (const float*)d_in[5];
    const float* k_bias  = (const float*)d_in[6];
    const float* Wv      = (const float*)d_in[7];
    const float* v_scale = (const float*)d_in[8];
    const float* v_bias  = (const float*)d_in[9];
    const float* Wp      = (const float*)d_in[10];
    const float* bp      = (const float*)d_in[11];
    const float* p_scale = (const float*)d_in[12];
    const float* p_bias  = (const float*)d_in[13];
    float* out = (float*)d_out;

    __half *xsB, *qsp, *ksp, *vsp, *x2T, *wsplit;
    float *gscale, *gbias;
    cudaGetSymbolAddress((void**)&xsB,    g_xsB);
    cudaGetSymbolAddress((void**)&qsp,    g_qs);
    cudaGetSymbolAddress((void**)&ksp,    g_ks);
    cudaGetSymbolAddress((void**)&vsp,    g_vs);
    cudaGetSymbolAddress((void**)&x2T,    g_x2T);
    cudaGetSymbolAddress((void**)&wsplit, g_wsplit);
    cudaGetSymbolAddress((void**)&gscale, g_scale);
    cudaGetSymbolAddress((void**)&gbias,  g_bias);

    const int SMEM_BYTES = 2 * STAGE_BYTES;   // 73728
    cudaFuncSetAttribute(gemm_hmma_kernel<0>, cudaFuncAttributeMaxDynamicSharedMemorySize, SMEM_BYTES);
    cudaFuncSetAttribute(gemm_hmma_kernel<1>, cudaFuncAttributeMaxDynamicSharedMemorySize, SMEM_BYTES);
    cudaFuncSetAttribute(attn_x2_kernel, cudaFuncAttributeMaxDynamicSharedMemorySize, FA_TOTAL);

    // 0+1 merged: LIF+transpose (blocks 0..1023) + weight split (1024..2047)
    prep_kernel<<<2048, 256>>>(x, xsB, Wq, Wk, Wv, Wp, wsplit,
                               q_scale, q_bias, k_scale, k_bias, v_scale, v_bias,
                               gscale, gbias);

    // 2. q/k/v conv + BN + LIF fused in GEMM epilogue -> q/k/v [t,b,c,n] + vout
    gemm_hmma_kernel<0><<<dim3(8, 12, 32), 256, SMEM_BYTES>>>(
        wsplit, xsB, qsp, ksp, vsp, out + TOTAL,
        gscale, gbias, nullptr, nullptr, nullptr, 0);

    // 3+4 fused: attn (smem) + x2 + LIF(0.5) -> x2T [tb][n][c]
    attn_x2_kernel<<<dim3(NH, B_), 256, FA_TOTAL>>>(ksp, vsp, qsp, x2T);

    // 5. proj conv (hi split) + BN + identity (r13 epilogue + .cs) -> out
    gemm_hmma_kernel<1><<<dim3(2, 4, 128), 256, SMEM_BYTES>>>(
        wsplit, x2T, nullptr, nullptr, nullptr, nullptr,
        p_scale, p_bias, bp, x, out, 1536);
}

// round 17
// speedup vs baseline: 1.0725x; 1.0725x over previous
#include <cuda_runtime.h>
#include <cuda_fp16.h>
#include <cstdint>

// Problem constants
#define T_    4
#define B_    32
#define C_    512
#define HW_   256
#define NH    8
#define HD    64
#define SLICE 4194304      // B*C*HW = one time slice
#define TOTAL 16777216     // T*B*C*HW
#define CN    131072       // C*HW per (t,b)

// ---------------------------------------------------------------------------
// helpers
// ---------------------------------------------------------------------------
__device__ __forceinline__ uint32_t smem_to_u32(const void* smem_ptr) {
    uint32_t addr;
    asm("{ .reg .u64 tmp; cvta.to.shared.u64 tmp, %1; cvt.u32.u64 %0, tmp; }"
        : "=r"(addr) : "l"(smem_ptr));
    return addr;
}

__device__ __forceinline__ void cp16(uint32_t dst, const void* src) {
    asm volatile("cp.async.ca.shared.global [%0], [%1], 16;" :: "r"(dst), "l"(src));
}

__device__ __forceinline__ void ldsm4(uint32_t* r, uint32_t addr) {
    asm volatile("ldmatrix.sync.aligned.m8n8.x4.shared.b16 {%0,%1,%2,%3}, [%4];"
                 : "=r"(r[0]), "=r"(r[1]), "=r"(r[2]), "=r"(r[3]) : "r"(addr));
}

__device__ __forceinline__ void ldsm4t(uint32_t* r, uint32_t addr) {
    asm volatile("ldmatrix.sync.aligned.m8n8.x4.trans.shared.b16 {%0,%1,%2,%3}, [%4];"
                 : "=r"(r[0]), "=r"(r[1]), "=r"(r[2]), "=r"(r[3]) : "r"(addr));
}

__device__ __forceinline__ void mma16816h(float* c, const uint32_t* a,
                                          uint32_t b0, uint32_t b1) {
    asm volatile(
        "mma.sync.aligned.m16n8k16.row.col.f32.f16.f16.f32 "
        "{%0,%1,%2,%3}, {%4,%5,%6,%7}, {%8,%9}, {%0,%1,%2,%3};"
        : "+f"(c[0]), "+f"(c[1]), "+f"(c[2]), "+f"(c[3])
        : "r"(a[0]), "r"(a[1]), "r"(a[2]), "r"(a[3]), "r"(b0), "r"(b1));
}

// ---------------------------------------------------------------------------
// Scratch (static device globals)
// ---------------------------------------------------------------------------
__device__ __half g_xsB[TOTAL];              // x spikes, per-b matrix [b][n'][c]
__device__ __half g_qs[TOTAL];               // q spikes, [t,b,c,n] fp16
__device__ __half g_ks[TOTAL];               // k spikes, [t,b,c,n] fp16
__device__ __half g_vs[TOTAL];               // v spikes, [t,b,c,n] fp16
__device__ __half g_x2T[TOTAL];              // x2 spikes, [tb][n][c] fp16
__device__ __half g_wsplit[2u * 2048u * 512u];      // [split: 0=mid',1=hi][2048][512]
__device__ float  g_scale[3 * C_];
__device__ float  g_bias [3 * C_];

// ---------------------------------------------------------------------------
// K1 (merged): blocks 0..1023  -> shortcut LIF + transpose (xsB [b][n'][c])
//              blocks 1024..2047 -> weight split (4 elems/thread) + sb concat
// ---------------------------------------------------------------------------
__global__ void prep_kernel(const float* __restrict__ x, __half* __restrict__ xsB,
                            const float* __restrict__ Wq, const float* __restrict__ Wk,
                            const float* __restrict__ Wv, const float* __restrict__ Wp,
                            __half* __restrict__ ws,
                            const float* __restrict__ qs, const float* __restrict__ qb,
                            const float* __restrict__ ks, const float* __restrict__ kb,
                            const float* __restrict__ vs, const float* __restrict__ vb,
                            float* __restrict__ gs, float* __restrict__ gb)
{
    __shared__ __half tile[64][65];
    int bid = blockIdx.x;
    int tid = threadIdx.x;

    if (bid >= 1024) {
        int base = (bid - 1024) * 1024 + tid * 4;
        int r = base >> 9;
        int kk = base & 511;
        const float* W = (r < 512) ? Wq : (r < 1024) ? Wk : (r < 1536) ? Wv : Wp;
        const float4 w4 = *(const float4*)&W[(size_t)(r & 511) * 512 + kk];
        const float wv[4] = {w4.x, w4.y, w4.z, w4.w};
        __half hi4[4], mid4[4];
#pragma unroll
        for (int u = 0; u < 4; u++) {
            __half hi = __float2half_rn(wv[u]);
            float r1 = wv[u] - __half2float(hi);
            hi4[u] = hi;
            mid4[u] = __float2half_rn(r1 * 4096.0f);
        }
        *(uint2*)&ws[base]             = *(uint2*)mid4;
        *(uint2*)&ws[1048576u + base]  = *(uint2*)hi4;

        int i = (bid - 1024) * 256 + tid;
        if (i < 512) {
            gs[i] = qs[i];               gb[i] = qb[i];
            gs[i + 512]  = ks[i];        gb[i + 512]  = kb[i];
            gs[i + 1024] = vs[i];        gb[i + 1024] = vb[i];
        }
        return;
    }

    int nblk = bid & 3, cblk = (bid >> 2) & 7, b = bid >> 5;

    float v[16];
#pragma unroll
    for (int p = 0; p < 16; p++) v[p] = 0.f;

    __half* D = xsB + (size_t)b * (1024 * 512);

#pragma unroll
    for (int t = 0; t < T_; t++) {
        if (t) __syncthreads();
#pragma unroll
        for (int p = 0; p < 16; p++) {
            int c_l = p * 4 + (tid >> 6), n_l = tid & 63;
            float xv = x[(size_t)t * SLICE +
                         ((size_t)(b * C_ + cblk * 64 + c_l)) * HW_ + nblk * 64 + n_l];
            v[p] = v[p] + (xv - v[p]) * 0.5f;
            float s = (v[p] >= 1.0f) ? 1.0f : 0.0f;
            if (s != 0.f) v[p] = 0.f;
            tile[c_l][n_l] = __float2half(s);
        }
        __syncthreads();
#pragma unroll
        for (int p = 0; p < 16; p++) {
            int c_l = tid & 63, n_l = p * 4 + (tid >> 6);
            int n = nblk * 64 + n_l;
            int nprime = (n >> 3) * 32 + t * 8 + (n & 7);
            D[(size_t)nprime * C_ + cblk * 64 + c_l] = tile[c_l][n_l];
        }
    }
}

// ---------------------------------------------------------------------------
// HMMA GEMM: CTA 128x128, 2x4 warps of 64x32, TWO-stage double buffer (r6 loop)
// MODE 0: qkv, 16 stages (8 mid' + 8 hi, exact). Epilogue: BN -> LIF(vth=1)
//         -> q/k/v [t,b,c,n] + vout. grid (8 nblk, 12 mtile, 32 b)
// MODE 1: proj, hi-split only (8 stages). Direct r13 epilogue. grid (2,4,128)
// ---------------------------------------------------------------------------
#define STAGE_BYTES 36864
#define A_BYTES     18432
#define SM_STRIDE   136          // halves; 272B row stride (MODE0 epilogue)

template<int MODE>
__global__ void __launch_bounds__(256, 2) gemm_hmma_kernel(
    const __half* __restrict__ wsplit,            // [2][2048][512]
    const __half* __restrict__ Bmat,              // MODE0: xsB ; MODE1: x2T
    __half* __restrict__ qsp, __half* __restrict__ ksp, __half* __restrict__ vsp,
    float* __restrict__ vout,
    const float* __restrict__ scale, const float* __restrict__ bias,
    const float* __restrict__ cbias, const float* __restrict__ identity,
    float* __restrict__ outp, int wrow_base)
{
    constexpr int NS = (MODE == 0) ? 16 : 8;
    extern __shared__ __align__(128) char smem[];
    uint32_t smem_u = smem_to_u32(smem);
    const int tid = threadIdx.x;
    const int wid = tid >> 5, lane = tid & 31;
    const int wm = wid >> 2, wn = wid & 3;         // 2 x 4 warp grid, 64x32 tiles
    const int n0 = blockIdx.x * 128;
    const int m0 = blockIdx.y * 128;
    const int bz = blockIdx.z;
    const char* Bbase = (MODE == 0)
        ? (const char*)(Bmat + (size_t)bz * (1024 * 512))
        : (const char*)(Bmat + (size_t)bz * CN);

    float acc[4][4][4];
#pragma unroll
    for (int i = 0; i < 4; i++)
#pragma unroll
        for (int j = 0; j < 4; j++)
#pragma unroll
            for (int e = 0; e < 4; e++) acc[i][j][e] = 0.f;

    auto cp_stage = [&](int s) {
        int buf = s & 1;
        int split = (MODE == 0) ? (s >> 3) : 1;   // MODE1: hi only
        int kA = (s & 7) << 6;
        const char* Ag = (const char*)wsplit
                       + ((size_t)split * 2048 + (size_t)(wrow_base + m0)) * 1024
                       + (size_t)kA * 2;
        const char* Bg = Bbase + (size_t)n0 * 1024 + (size_t)kA * 2;
        uint32_t sA = smem_u + buf * STAGE_BYTES;
        uint32_t sB = sA + A_BYTES;
#pragma unroll
        for (int p = 0; p < 4; p++) {
            int lin = p * 256 + tid;
            int r = lin >> 3, sg = lin & 7;
            cp16(sA + r * 144 + sg * 16, Ag + (size_t)r * 1024 + sg * 16);
            cp16(sB + r * 144 + sg * 16, Bg + (size_t)r * 1024 + sg * 16);
        }
        asm volatile("cp.async.commit_group;");
    };

    cp_stage(0);

    for (int s = 0; s < NS; s++) {
        if (s + 1 < NS) {
            cp_stage(s + 1);
            asm volatile("cp.async.wait_group 1;");
        } else {
            asm volatile("cp.async.wait_group 0;");
        }
        __syncthreads();

        uint32_t sA = smem_u + (s & 1) * STAGE_BYTES;
        uint32_t sB = sA + A_BYTES;

#pragma unroll
        for (int kk = 0; kk < 4; kk++) {
            uint32_t a[4][4];
#pragma unroll
            for (int i = 0; i < 4; i++) {
                uint32_t row = wm * 64 + i * 16 + (lane & 15);
                uint32_t col = kk * 16 + ((lane >> 4) << 3);
                ldsm4(a[i], sA + (row * 72 + col) * 2);
            }
            uint32_t bf[2][4];
#pragma unroll
            for (int j2 = 0; j2 < 2; j2++) {
                uint32_t row = wn * 32 + j2 * 16 + (lane & 7) + ((lane >> 4) << 3);
                uint32_t col = kk * 16 + (((lane >> 3) & 1) << 3);
                ldsm4(bf[j2], sB + (row * 72 + col) * 2);
            }
#pragma unroll
            for (int i = 0; i < 4; i++)
#pragma unroll
                for (int jj = 0; jj < 4; jj++) {
                    uint32_t b0 = bf[jj >> 1][(jj & 1) * 2 + 0];
                    uint32_t b1 = bf[jj >> 1][(jj & 1) * 2 + 1];
                    mma16816h(acc[i][jj], a[i], b0, b1);
                }
        }
        if (MODE == 0 && s == 7) {
#pragma unroll
            for (int i = 0; i < 4; i++)
#pragma unroll
                for (int j = 0; j < 4; j++)
#pragma unroll
                    for (int e = 0; e < 4; e++) acc[i][j][e] *= 0.000244140625f;
        }
        __syncthreads();
    }

    int g = lane >> 2, tg = lane & 3;

    if (MODE == 0) {
        // ---- BN + LIF (vth=1) in registers: jj == t ----
        __half (*sm)[SM_STRIDE] = (__half(*)[SM_STRIDE])smem;
#pragma unroll
        for (int i = 0; i < 4; i++) {
#pragma unroll
            for (int eh = 0; eh < 2; eh++) {
                int rl = wm * 64 + i * 16 + g + eh * 8;
                float sc = scale[m0 + rl], bi = bias[m0 + rl];
#pragma unroll
                for (int e1 = 0; e1 < 2; e1++) {
                    int nl = wn * 8 + 2 * tg + e1;        // n_local 0..31
                    float v = 0.f;
#pragma unroll
                    for (int t = 0; t < T_; t++) {
                        float xv = acc[i][t][eh * 2 + e1] * sc + bi;
                        v = v + (xv - v) * 0.5f;
                        float ss = (v >= 1.0f) ? 1.0f : 0.0f;
                        if (ss != 0.f) v = 0.f;
                        sm[rl][t * 32 + nl] = __float2half(ss);
                    }
                }
            }
        }
        __syncthreads();

        int tt   = blockIdx.y >> 2;      // 0 q, 1 k, 2 v
        int msub = blockIdx.y & 3;       // 128-row block within tensor
        int b    = bz;
        int nb   = blockIdx.x;           // n base = nb*32

        __half* base = (tt == 0) ? qsp : (tt == 1) ? ksp : vsp;
#pragma unroll
        for (int p = 0; p < 2; p++) {
            int rid = p * 256 + tid;       // 0..511
            int t = rid >> 7, cl = rid & 127;
            const uint4* srow = (const uint4*)&sm[cl][t * 32];
            __half* dst = base + (size_t)t * SLICE
                        + ((size_t)(b * C_ + msub * 128 + cl)) * HW_ + nb * 32;
#pragma unroll
            for (int u = 0; u < 4; u++) ((uint4*)dst)[u] = srow[u];
        }
        if (tt == 2) {
            // vout fp32 [t,b,h,n,hd]
            int t = tid >> 6, rem = tid & 63;
            int hl = rem >> 5, n = rem & 31;
            int h = msub * 2 + hl;
            float* dst = vout + ((((size_t)(t * 32 + b) * NH + h) * HW_) + nb * 32 + n) * HD;
#pragma unroll
            for (int c4 = 0; c4 < 16; c4++) {
                float4 f;
                f.x = __half2float(sm[hl * 64 + c4 * 4 + 0][t * 32 + n]);
                f.y = __half2float(sm[hl * 64 + c4 * 4 + 1][t * 32 + n]);
                f.z = __half2float(sm[hl * 64 + c4 * 4 + 2][t * 32 + n]);
                f.w = __half2float(sm[hl * 64 + c4 * 4 + 3][t * 32 + n]);
                ((float4*)dst)[c4] = f;
            }
        }
    } else {
        // ---- proj epilogue (r13 form) ----
#pragma unroll
        for (int i = 0; i < 4; i++) {
            int mloc = m0 + wm * 64 + i * 16 + g;
#pragma unroll
            for (int half = 0; half < 2; half++) {
                int c = mloc + half * 8;
                float sc = scale[c], bi = bias[c], cb = cbias[c];
                float* dst = outp + (size_t)bz * CN + (size_t)c * HW_;
                const float* idp = identity + (size_t)bz * CN + (size_t)c * HW_;
#pragma unroll
                for (int jj = 0; jj < 4; jj++) {
                    int col = n0 + wn * 32 + jj * 8 + 2 * tg;
                    float2 id2 = *(const float2*)&idp[col];
                    float2 v2;
                    v2.x = (acc[i][jj][half * 2 + 0] + cb) * sc + bi + id2.x;
                    v2.y = (acc[i][jj][half * 2 + 1] + cb) * sc + bi + id2.y;
                    *(float2*)&dst[col] = v2;
                }
            }
        }
    }
}

// ---------------------------------------------------------------------------
// FUSED attn + x2 kernel, one CTA per (h, b), 256 threads. (r13, unchanged)
// ---------------------------------------------------------------------------
#define FA_AT    0
#define FA_WORK  18432
#define FA_SQ    18432
#define FA_SX    35840
#define FA_TOTAL 55296
#define SQN      136

__global__ void __launch_bounds__(256) attn_x2_kernel(
    const __half* __restrict__ ksp, const __half* __restrict__ vsp,
    const __half* __restrict__ qsp, __half* __restrict__ x2T)
{
    extern __shared__ __align__(128) char fsm[];
    uint32_t smem_u = smem_to_u32(fsm);
    int h = blockIdx.x, b = blockIdx.y;
    int tid = threadIdx.x;
    int wid = tid >> 5, lane = tid & 31;
    int g = lane >> 2, tg = lane & 3;

    // ---------------- Phase A: attn ----------------
    {
        int group = tid >> 7;
        int gtid = tid & 127;
        int gwid = gtid >> 5;
        uint32_t sv_u = smem_u + FA_WORK + group * 18432;
        uint32_t sk_u = sv_u + 9216;
        char* sv_c = fsm + FA_WORK + group * 18432;
        char* sk_c = sv_c + 9216;

        float acc[8][4];
#pragma unroll
        for (int j = 0; j < 8; j++)
#pragma unroll
            for (int e = 0; e < 4; e++) acc[j][e] = 0.f;

        for (int st = 0; st < 8; st++) {
            int t = group * 2 + (st >> 2);
            int n0 = (st & 3) * 64;
            size_t base = (size_t)t * SLICE + ((size_t)(b * C_ + h * HD)) * HW_ + n0;
#pragma unroll
            for (int l = 0; l < 4; l++) {
                int lin = l * 128 + gtid;
                int r = lin >> 3, sg = lin & 7;
                *(uint4*)(sv_c + r * 144 + sg * 16) =
                    *(const uint4*)(vsp + base + (size_t)r * HW_ + sg * 8);
                *(uint4*)(sk_c + r * 144 + sg * 16) =
                    *(const uint4*)(ksp + base + (size_t)r * HW_ + sg * 8);
            }
            __syncthreads();

#pragma unroll
            for (int kk = 0; kk < 4; kk++) {
                uint32_t a[4];
                {
                    uint32_t row = gwid * 16 + (lane & 15);
                    uint32_t col = kk * 16 + ((lane >> 4) << 3);
                    ldsm4(a, sv_u + (row * 72 + col) * 2);
                }
                uint32_t bf[4][4];
#pragma unroll
                for (int j2 = 0; j2 < 4; j2++) {
                    uint32_t row = j2 * 16 + (lane & 7) + ((lane >> 4) << 3);
                    uint32_t col = kk * 16 + (((lane >> 3) & 1) << 3);
                    ldsm4(bf[j2], sk_u + (row * 72 + col) * 2);
                }
#pragma unroll
                for (int j = 0; j < 8; j++)
                    mma16816h(acc[j], a, bf[j >> 1][(j & 1) * 2], bf[j >> 1][(j & 1) * 2 + 1]);
            }
            __syncthreads();
        }

        char* at_c = fsm + FA_AT + group * 9216;
#pragma unroll
        for (int j = 0; j < 8; j++)
#pragma unroll
            for (int e = 0; e < 2; e++) {
                int row = gwid * 16 + g + e * 8;
                int col = j * 8 + tg * 2;
                __half2 h2 = __floats2half2_rn(acc[j][e * 2] * 0.0625f,
                                               acc[j][e * 2 + 1] * 0.0625f);
                *(__half2*)(at_c + (row * 72 + col) * 2) = h2;
            }
    }
    __syncthreads();

    // ---------------- Phase B: x2 ----------------
    int wm = wid >> 1, wn = wid & 1;
    uint32_t sq_u = smem_u + FA_SQ;
    __half (*sx)[72] = (__half(*)[72])(fsm + FA_SX);

    for (int nhalf = 0; nhalf < 2; nhalf++) {
        float mem[8][4];
#pragma unroll
        for (int j = 0; j < 8; j++)
#pragma unroll
            for (int e = 0; e < 4; e++) mem[j][e] = 0.f;

#pragma unroll
        for (int t = 0; t < T_; t++) {
            uint32_t sa_u = smem_u + FA_AT + (t >> 1) * 9216;
            {
                const __half* qp = qsp + (size_t)t * SLICE
                                 + ((size_t)(b * C_ + h * HD)) * HW_ + nhalf * 128;
#pragma unroll
                for (int l = 0; l < 4; l++) {
                    int lin = l * 256 + tid;
                    int r = lin >> 4, sg = lin & 15;
                    *(uint4*)(fsm + FA_SQ + r * (SQN * 2) + sg * 16) =
                        *(const uint4*)(qp + (size_t)r * HW_ + sg * 8);
                }
            }
            __syncthreads();

            float acc[8][4];
#pragma unroll
            for (int j = 0; j < 8; j++)
#pragma unroll
                for (int e = 0; e < 4; e++) acc[j][e] = 0.f;

#pragma unroll
            for (int kk = 0; kk < 4; kk++) {
                uint32_t a[4];
                {
                    uint32_t row = wm * 16 + (lane & 15);
                    uint32_t col = kk * 16 + ((lane >> 4) << 3);
                    ldsm4(a, sa_u + (row * 72 + col) * 2);
                }
                uint32_t bf[4][4];
#pragma unroll
                for (int j2 = 0; j2 < 4; j2++) {
                    uint32_t krow = kk * 16 + (((lane >> 3) & 1) << 3) + (lane & 7);
                    uint32_t ncol = wn * 64 + j2 * 16 + ((lane >> 4) << 3);
                    ldsm4t(bf[j2], sq_u + (krow * SQN + ncol) * 2);
                }
#pragma unroll
                for (int j = 0; j < 8; j++)
                    mma16816h(acc[j], a, bf[j >> 1][(j & 1) * 2], bf[j >> 1][(j & 1) * 2 + 1]);
            }

#pragma unroll
            for (int j = 0; j < 8; j++)
#pragma unroll
                for (int e = 0; e < 4; e++) {
                    float xv = acc[j][e];
                    mem[j][e] = mem[j][e] + (xv - mem[j][e]) * 0.5f;
                    float s = (mem[j][e] >= 0.5f) ? 1.0f : 0.0f;
                    if (s != 0.f) mem[j][e] = 0.f;
                    int n = wn * 64 + j * 8 + tg * 2 + (e & 1);
                    int de = wm * 16 + g + ((e >> 1) << 3);
                    sx[n][de] = __float2half(s);
                }
            __syncthreads();

            {
                __half* obase = x2T + ((size_t)(t * B_ + b) * HW_ + nhalf * 128) * C_ + h * HD;
#pragma unroll
                for (int l = 0; l < 2; l++) {
                    int idx = l * 256 + tid;
                    int n = idx >> 2, seg = idx & 3;
                    *(uint4*)(obase + (size_t)n * C_ + seg * 16) =
                        *(const uint4*)(&sx[n][seg * 16]);
                }
            }
            __syncthreads();
        }
    }
}

// ---------------------------------------------------------------------------
extern "C" void kernel_launch(void* const* d_in, const int* in_sizes, int n_in,
                              void* d_out, int out_size)
{
    const float* x       = (const float*)d_in[0];
    const float* Wq      = (const float*)d_in[1];
    const float* q_scale = (const float*)d_in[2];
    const float* q_bias  = (const float*)d_in[3];
    const float* Wk      = (const float*)d_in[4];
    const float* k_scale = (const float*)d_in[5];
    const float* k_bias  = (const float*)d_in[6];
    const float* Wv      = (const float*)d_in[7];
    const float* v_scale = (const float*)d_in[8];
    const float* v_bias  = (const float*)d_in[9];
    const float* Wp      = (const float*)d_in[10];
    const float* bp      = (const float*)d_in[11];
    const float* p_scale = (const float*)d_in[12];
    const float* p_bias  = (const float*)d_in[13];
    float* out = (float*)d_out;

    __half *xsB, *qsp, *ksp, *vsp, *x2T, *wsplit;
    float *gscale, *gbias;
    cudaGetSymbolAddress((void**)&xsB,    g_xsB);
    cudaGetSymbolAddress((void**)&qsp,    g_qs);
    cudaGetSymbolAddress((void**)&ksp,    g_ks);
    cudaGetSymbolAddress((void**)&vsp,    g_vs);
    cudaGetSymbolAddress((void**)&x2T,    g_x2T);
    cudaGetSymbolAddress((void**)&wsplit, g_wsplit);
    cudaGetSymbolAddress((void**)&gscale, g_scale);
    cudaGetSymbolAddress((void**)&gbias,  g_bias);

    const int SMEM_BYTES = 2 * STAGE_BYTES;   // 73728
    cudaFuncSetAttribute(gemm_hmma_kernel<0>, cudaFuncAttributeMaxDynamicSharedMemorySize, SMEM_BYTES);
    cudaFuncSetAttribute(gemm_hmma_kernel<1>, cudaFuncAttributeMaxDynamicSharedMemorySize, SMEM_BYTES);
    cudaFuncSetAttribute(attn_x2_kernel, cudaFuncAttributeMaxDynamicSharedMemorySize, FA_TOTAL);

    // 0+1 merged: LIF+transpose (blocks 0..1023) + weight split (1024..2047)
    prep_kernel<<<2048, 256>>>(x, xsB, Wq, Wk, Wv, Wp, wsplit,
                               q_scale, q_bias, k_scale, k_bias, v_scale, v_bias,
                               gscale, gbias);

    // 2. q/k/v conv + BN + LIF fused in GEMM epilogue -> q/k/v [t,b,c,n] + vout
    gemm_hmma_kernel<0><<<dim3(8, 12, 32), 256, SMEM_BYTES>>>(
        wsplit, xsB, qsp, ksp, vsp, out + TOTAL,
        gscale, gbias, nullptr, nullptr, nullptr, 0);

    // 3+4 fused: attn (smem) + x2 + LIF(0.5) -> x2T [tb][n][c]
    attn_x2_kernel<<<dim3(NH, B_), 256, FA_TOTAL>>>(ksp, vsp, qsp, x2T);

    // 5. proj conv (hi split) + BN + identity (r13 epilogue) -> out
    gemm_hmma_kernel<1><<<dim3(2, 4, 128), 256, SMEM_BYTES>>>(
        wsplit, x2T, nullptr, nullptr, nullptr, nullptr,
        p_scale, p_bias, bp, x, out, 1536);
}